// round 1
// baseline (speedup 1.0000x reference)
#include <cuda_runtime.h>

#define BB 2
#define LL 384
#define DD 1280
#define HH 256
#define NB 10

// scratch for projections (device globals: no allocation allowed)
__device__ float g_xi[BB * LL * HH];
__device__ float g_xj[BB * LL * HH];

// ---------------------------------------------------------------------------
// Kernel A: proj = x @ W + b   (z = 0 -> Wi/bi -> g_xi, z = 1 -> Wj/bj -> g_xj)
// M = B*L = 768, K = 1280, N = 256. Tile 64x64, BK = 16, 256 threads, 4x4/thread.
// ---------------------------------------------------------------------------
__global__ __launch_bounds__(256) void proj_kernel(
    const float* __restrict__ x,
    const float* __restrict__ Wi, const float* __restrict__ bi,
    const float* __restrict__ Wj, const float* __restrict__ bj)
{
    const int zz = blockIdx.z;
    const float* __restrict__ W    = zz ? Wj : Wi;
    const float* __restrict__ bias = zz ? bj : bi;
    float* __restrict__ out        = zz ? g_xj : g_xi;

    __shared__ __align__(16) float As[16][68];  // [k][m], pad 68 keeps float4 align
    __shared__ __align__(16) float Bs[16][68];  // [k][n]

    const int tid = threadIdx.x;
    const int tx = tid & 15;       // n-group 0..15
    const int ty = tid >> 4;       // m-group 0..15
    const int m0 = blockIdx.x * 64;
    const int n0 = blockIdx.y * 64;

    float acc[4][4] = {};

    for (int k0 = 0; k0 < DD; k0 += 16) {
        // A tile: x[m0+r][k0+kk] -> As[kk][r]
        {
            const int kk = tid & 15;
            const int r  = tid >> 4;   // 0..15
            #pragma unroll
            for (int l = 0; l < 4; l++)
                As[kk][r + 16 * l] = x[(m0 + r + 16 * l) * DD + k0 + kk];
        }
        // B tile: W[k0+kk][n0+n] -> Bs[kk][n]
        {
            const int n   = tid & 63;
            const int kk4 = tid >> 6;  // 0..3
            #pragma unroll
            for (int l = 0; l < 4; l++)
                Bs[kk4 + 4 * l][n] = W[(k0 + kk4 + 4 * l) * HH + n0 + n];
        }
        __syncthreads();

        #pragma unroll
        for (int kk = 0; kk < 16; kk++) {
            const float4 av = *(const float4*)&As[kk][ty * 4];
            const float4 bv = *(const float4*)&Bs[kk][tx * 4];
            const float a[4] = {av.x, av.y, av.z, av.w};
            const float b[4] = {bv.x, bv.y, bv.z, bv.w};
            #pragma unroll
            for (int i = 0; i < 4; i++)
                #pragma unroll
                for (int j = 0; j < 4; j++)
                    acc[i][j] += a[i] * b[j];
        }
        __syncthreads();
    }

    #pragma unroll
    for (int j = 0; j < 4; j++) {
        const float bv = bias[n0 + tx * 4 + j];
        #pragma unroll
        for (int i = 0; i < 4; i++)
            out[(m0 + ty * 4 + i) * HH + n0 + tx * 4 + j] = acc[i][j] + bv;
    }
}

// ---------------------------------------------------------------------------
// Kernel B: out[b,i,j,n] = sum_k relu(xi[b,i,k]*xj[b,j,k]) * Wo[k,n] + bo[n]
// Block = 32x32 (i,j) tile, 256 threads, each thread 2x2 pairs x 10 bins.
// k staged in chunks of 64 through smem. FMA-pipe bound by construction.
// ---------------------------------------------------------------------------
#define TI 32
#define TJ 32
#define KC 64

__global__ __launch_bounds__(256) void pair_kernel(
    const float* __restrict__ Wo, const float* __restrict__ bo,
    float* __restrict__ out)
{
    __shared__ float sxi[TI][KC + 1];   // pad -> conflict-free [row][k] reads
    __shared__ float sxj[TJ][KC + 1];
    __shared__ float sWo[KC][NB];

    const int b  = blockIdx.z;
    const int i0 = blockIdx.y * TI;
    const int j0 = blockIdx.x * TJ;

    const int tid = threadIdx.x;
    const int tx = tid & 15;   // j-group
    const int ty = tid >> 4;   // i-group

    const float* __restrict__ xi = g_xi + (b * LL + i0) * HH;
    const float* __restrict__ xj = g_xj + (b * LL + j0) * HH;

    float acc[2][2][NB] = {};

    for (int k0 = 0; k0 < HH; k0 += KC) {
        // stage xi / xj chunk: 32 rows x 64 k each
        {
            const int c = tid & 63;     // k within chunk
            const int r = tid >> 6;     // 0..3
            #pragma unroll
            for (int l = 0; l < 8; l++)
                sxi[r + 4 * l][c] = xi[(r + 4 * l) * HH + k0 + c];
            #pragma unroll
            for (int l = 0; l < 8; l++)
                sxj[r + 4 * l][c] = xj[(r + 4 * l) * HH + k0 + c];
        }
        // stage Wo chunk: 64 x 10
        for (int idx = tid; idx < KC * NB; idx += 256) {
            const int kk = idx / NB, n = idx % NB;
            sWo[kk][n] = Wo[(k0 + kk) * NB + n];
        }
        __syncthreads();

        #pragma unroll 8
        for (int kk = 0; kk < KC; kk++) {
            const float a0 = sxi[ty][kk];
            const float a1 = sxi[ty + 16][kk];
            const float b0 = sxj[tx][kk];
            const float b1 = sxj[tx + 16][kk];
            const float p00 = fmaxf(a0 * b0, 0.f);
            const float p01 = fmaxf(a0 * b1, 0.f);
            const float p10 = fmaxf(a1 * b0, 0.f);
            const float p11 = fmaxf(a1 * b1, 0.f);
            #pragma unroll
            for (int n = 0; n < NB; n++) {
                const float w = sWo[kk][n];
                acc[0][0][n] += p00 * w;
                acc[0][1][n] += p01 * w;
                acc[1][0][n] += p10 * w;
                acc[1][1][n] += p11 * w;
            }
        }
        __syncthreads();
    }

    // epilogue: add bo, write out[b][i][j][n]
    float bov[NB];
    #pragma unroll
    for (int n = 0; n < NB; n++) bov[n] = bo[n];

    #pragma unroll
    for (int ii = 0; ii < 2; ii++) {
        #pragma unroll
        for (int jj = 0; jj < 2; jj++) {
            const int i = i0 + ty + ii * 16;
            const int j = j0 + tx + jj * 16;
            float* o = out + ((size_t)b * LL * LL + (size_t)i * LL + j) * NB;
            #pragma unroll
            for (int n = 0; n < NB; n++)
                o[n] = acc[ii][jj][n] + bov[n];
        }
    }
}

// ---------------------------------------------------------------------------
// launch
// ---------------------------------------------------------------------------
extern "C" void kernel_launch(void* const* d_in, const int* in_sizes, int n_in,
                              void* d_out, int out_size)
{
    const float* x  = (const float*)d_in[0];
    const float* Wi = (const float*)d_in[1];
    const float* bi = (const float*)d_in[2];
    const float* Wj = (const float*)d_in[3];
    const float* bj = (const float*)d_in[4];
    const float* Wo = (const float*)d_in[5];
    const float* bo = (const float*)d_in[6];
    float* out = (float*)d_out;

    // Kernel A: projections. M=768 -> 12 tiles, N=256 -> 4 tiles, z=2 weights.
    dim3 gA(12, 4, 2);
    proj_kernel<<<gA, 256>>>(x, Wi, bi, Wj, bj);

    // Kernel B: pair + relu + bin projection. 12x12 (j,i) tiles x 2 batches.
    dim3 gB(LL / TJ, LL / TI, BB);
    pair_kernel<<<gB, 256>>>(Wo, bo, out);
}

// round 2
// speedup vs baseline: 2.0123x; 2.0123x over previous
#include <cuda_runtime.h>

#define BB 2
#define LL 384
#define DD 1280
#define HH 256
#define NB 10

// scratch for projections (device globals: no allocation allowed)
__device__ float g_xi[BB * LL * HH];
__device__ float g_xj[BB * LL * HH];

// ---------------------------------------------------------------------------
// zero-init for split-K atomic accumulation (xi+xj = 393216 floats = 98304 f4)
// ---------------------------------------------------------------------------
__global__ void zero_kernel()
{
    const int idx = blockIdx.x * blockDim.x + threadIdx.x;      // 0 .. 98303
    float4* p = (idx < 49152) ? (float4*)g_xi : (float4*)g_xj;
    const int off = (idx < 49152) ? idx : idx - 49152;
    p[off] = make_float4(0.f, 0.f, 0.f, 0.f);
}

// ---------------------------------------------------------------------------
// Kernel A: merged projection GEMM, M=768, N=512 (Wi|Wj), K=1280, split-K x3.
// Tile 64x64, BK=16, 256 threads, 4x4 per thread. atomicAdd epilogue.
// grid = (12 mtiles, 8 ntiles, 3 ksplit) = 288 CTAs -> all resident.
// ---------------------------------------------------------------------------
__global__ __launch_bounds__(256) void proj_kernel(
    const float* __restrict__ x,
    const float* __restrict__ Wi, const float* __restrict__ bi,
    const float* __restrict__ Wj, const float* __restrict__ bj)
{
    const int nglob0 = blockIdx.y * 64;
    const bool second = (nglob0 >= HH);
    const float* __restrict__ W    = second ? Wj : Wi;
    const float* __restrict__ bias = second ? bj : bi;
    float* __restrict__ out        = second ? g_xj : g_xi;
    const int n0 = second ? (nglob0 - HH) : nglob0;

    const int kz   = blockIdx.z;                 // 0,1,2
    const int it0  = kz * 27;                    // BK-iteration start
    const int nIt  = (kz == 2) ? 26 : 27;        // 27+27+26 = 80 iters total

    __shared__ __align__(16) float As[16][68];   // [k][m]
    __shared__ __align__(16) float Bs[16][68];   // [k][n]

    const int tid = threadIdx.x;
    const int tx = tid & 15;        // n-group
    const int ty = tid >> 4;        // m-group
    const int m0 = blockIdx.x * 64;

    float acc[4][4] = {};

    for (int it = it0; it < it0 + nIt; it++) {
        const int k0 = it * 16;
        // A tile: x[m0+r][k0+kk] -> As[kk][r]
        {
            const int kk = tid & 15;
            const int r  = tid >> 4;
            #pragma unroll
            for (int l = 0; l < 4; l++)
                As[kk][r + 16 * l] = x[(m0 + r + 16 * l) * DD + k0 + kk];
        }
        // B tile: W[k0+kk][n0+n] -> Bs[kk][n]
        {
            const int n   = tid & 63;
            const int kk4 = tid >> 6;
            #pragma unroll
            for (int l = 0; l < 4; l++)
                Bs[kk4 + 4 * l][n] = W[(k0 + kk4 + 4 * l) * HH + n0 + n];
        }
        __syncthreads();

        #pragma unroll
        for (int kk = 0; kk < 16; kk++) {
            const float4 av = *(const float4*)&As[kk][ty * 4];
            const float4 bv = *(const float4*)&Bs[kk][tx * 4];
            const float a[4] = {av.x, av.y, av.z, av.w};
            const float b[4] = {bv.x, bv.y, bv.z, bv.w};
            #pragma unroll
            for (int i = 0; i < 4; i++)
                #pragma unroll
                for (int j = 0; j < 4; j++)
                    acc[i][j] += a[i] * b[j];
        }
        __syncthreads();
    }

    #pragma unroll
    for (int j = 0; j < 4; j++) {
        const float bv = (kz == 0) ? bias[n0 + tx * 4 + j] : 0.f;
        #pragma unroll
        for (int i = 0; i < 4; i++)
            atomicAdd(&out[(m0 + ty * 4 + i) * HH + n0 + tx * 4 + j],
                      acc[i][j] + bv);
    }
}

// ---------------------------------------------------------------------------
// Kernel B: out[b,i,j,n] = sum_k relu(xi[b,i,k]*xj[b,j,k]) * Wo[k,n] + bo[n]
// 32x32 (i,j) tile, 256 threads, 2x2 pairs/thread, k processed 4 at a time
// with float2 LDS everywhere. Stride-66 padding -> conflict-free.
// ---------------------------------------------------------------------------
#define TI 32
#define TJ 32
#define KC 64
#define PSTR 66   // padded row stride (floats), even -> float2-aligned

__global__ __launch_bounds__(256, 2) void pair_kernel(
    const float* __restrict__ Wo, const float* __restrict__ bo,
    float* __restrict__ out)
{
    __shared__ __align__(8) float sxi[TI * PSTR];
    __shared__ __align__(8) float sxj[TJ * PSTR];
    __shared__ __align__(8) float sWo[KC * NB];

    const int b  = blockIdx.z;
    const int i0 = blockIdx.y * TI;
    const int j0 = blockIdx.x * TJ;

    const int tid = threadIdx.x;
    const int tx = tid & 15;   // j-group
    const int ty = tid >> 4;   // i-group

    const float* __restrict__ xi = g_xi + (b * LL + i0) * HH;
    const float* __restrict__ xj = g_xj + (b * LL + j0) * HH;

    float acc[2][2][NB] = {};

    for (int k0 = 0; k0 < HH; k0 += KC) {
        // stage xi / xj chunk with float2: 32 rows x 32 float2 = 1024 f2
        {
            const int c = tid & 31;     // float2 index within row (k/2)
            const int r = tid >> 5;     // 0..7
            #pragma unroll
            for (int l = 0; l < 4; l++) {
                const int row = r + 8 * l;
                *(float2*)&sxi[row * PSTR + 2 * c] =
                    *(const float2*)&xi[row * HH + k0 + 2 * c];
            }
            #pragma unroll
            for (int l = 0; l < 4; l++) {
                const int row = r + 8 * l;
                *(float2*)&sxj[row * PSTR + 2 * c] =
                    *(const float2*)&xj[row * HH + k0 + 2 * c];
            }
        }
        // stage Wo chunk: 64 x 10 = 320 float2
        {
            const float2* src = (const float2*)&Wo[k0 * NB];
            float2* dst = (float2*)sWo;
            if (tid < 256) dst[tid] = src[tid];
            if (tid < 64)  dst[256 + tid] = src[256 + tid];
        }
        __syncthreads();

        #pragma unroll
        for (int kk = 0; kk < KC; kk += 4) {
            const float2 a0A = *(const float2*)&sxi[ty * PSTR + kk];
            const float2 a0B = *(const float2*)&sxi[ty * PSTR + kk + 2];
            const float2 a1A = *(const float2*)&sxi[(ty + 16) * PSTR + kk];
            const float2 a1B = *(const float2*)&sxi[(ty + 16) * PSTR + kk + 2];
            const float2 b0A = *(const float2*)&sxj[tx * PSTR + kk];
            const float2 b0B = *(const float2*)&sxj[tx * PSTR + kk + 2];
            const float2 b1A = *(const float2*)&sxj[(tx + 16) * PSTR + kk];
            const float2 b1B = *(const float2*)&sxj[(tx + 16) * PSTR + kk + 2];

            float p[4][4];  // [pair 00,01,10,11][k-offset 0..3]
            p[0][0] = fmaxf(a0A.x * b0A.x, 0.f);
            p[0][1] = fmaxf(a0A.y * b0A.y, 0.f);
            p[0][2] = fmaxf(a0B.x * b0B.x, 0.f);
            p[0][3] = fmaxf(a0B.y * b0B.y, 0.f);
            p[1][0] = fmaxf(a0A.x * b1A.x, 0.f);
            p[1][1] = fmaxf(a0A.y * b1A.y, 0.f);
            p[1][2] = fmaxf(a0B.x * b1B.x, 0.f);
            p[1][3] = fmaxf(a0B.y * b1B.y, 0.f);
            p[2][0] = fmaxf(a1A.x * b0A.x, 0.f);
            p[2][1] = fmaxf(a1A.y * b0A.y, 0.f);
            p[2][2] = fmaxf(a1B.x * b0B.x, 0.f);
            p[2][3] = fmaxf(a1B.y * b0B.y, 0.f);
            p[3][0] = fmaxf(a1A.x * b1A.x, 0.f);
            p[3][1] = fmaxf(a1A.y * b1A.y, 0.f);
            p[3][2] = fmaxf(a1B.x * b1B.x, 0.f);
            p[3][3] = fmaxf(a1B.y * b1B.y, 0.f);

            #pragma unroll
            for (int kq = 0; kq < 4; kq++) {
                #pragma unroll
                for (int n2 = 0; n2 < 5; n2++) {
                    const float2 w = *(const float2*)&sWo[(kk + kq) * NB + 2 * n2];
                    acc[0][0][2 * n2]     += p[0][kq] * w.x;
                    acc[0][0][2 * n2 + 1] += p[0][kq] * w.y;
                    acc[0][1][2 * n2]     += p[1][kq] * w.x;
                    acc[0][1][2 * n2 + 1] += p[1][kq] * w.y;
                    acc[1][0][2 * n2]     += p[2][kq] * w.x;
                    acc[1][0][2 * n2 + 1] += p[2][kq] * w.y;
                    acc[1][1][2 * n2]     += p[3][kq] * w.x;
                    acc[1][1][2 * n2 + 1] += p[3][kq] * w.y;
                }
            }
        }
        __syncthreads();
    }

    // epilogue: add bo, write out[b][i][j][n] with float2 stores
    float bov[NB];
    #pragma unroll
    for (int n = 0; n < NB; n++) bov[n] = bo[n];

    #pragma unroll
    for (int ii = 0; ii < 2; ii++) {
        #pragma unroll
        for (int jj = 0; jj < 2; jj++) {
            const int i = i0 + ty + ii * 16;
            const int j = j0 + tx + jj * 16;
            float* o = out + ((size_t)b * LL * LL + (size_t)i * LL + j) * NB;
            #pragma unroll
            for (int n2 = 0; n2 < 5; n2++) {
                float2 v;
                v.x = acc[ii][jj][2 * n2]     + bov[2 * n2];
                v.y = acc[ii][jj][2 * n2 + 1] + bov[2 * n2 + 1];
                *(float2*)&o[2 * n2] = v;
            }
        }
    }
}

// ---------------------------------------------------------------------------
// launch
// ---------------------------------------------------------------------------
extern "C" void kernel_launch(void* const* d_in, const int* in_sizes, int n_in,
                              void* d_out, int out_size)
{
    const float* x  = (const float*)d_in[0];
    const float* Wi = (const float*)d_in[1];
    const float* bi = (const float*)d_in[2];
    const float* Wj = (const float*)d_in[3];
    const float* bj = (const float*)d_in[4];
    const float* Wo = (const float*)d_in[5];
    const float* bo = (const float*)d_in[6];
    float* out = (float*)d_out;

    // zero the split-K accumulators (98304 float4 across xi+xj)
    zero_kernel<<<384, 256>>>();

    // merged projection GEMM: 12 mtiles x 8 ntiles x 3 ksplits = 288 CTAs
    dim3 gA(12, 8, 3);
    proj_kernel<<<gA, 256>>>(x, Wi, bi, Wj, bj);

    // pair + relu + bin projection: 12x12 tiles x 2 batches = 288 CTAs
    dim3 gB(LL / TJ, LL / TI, BB);
    pair_kernel<<<gB, 256>>>(Wo, bo, out);
}

// round 4
// speedup vs baseline: 2.1210x; 1.0540x over previous
#include <cuda_runtime.h>
#include <cuda_bf16.h>
#include <cstdint>

#define BB 2
#define LL 384
#define DD 1280
#define HH 256
#define NB 10

// ---------------------------------------------------------------------------
// device globals (no allocation allowed)
// ---------------------------------------------------------------------------
__device__ float g_xi[BB * LL * HH];
__device__ float g_xj[BB * LL * HH];
// A-side split: variants 0=h+, 1=l+, 2=h-, 3=l-   [768][256] bf16 each
__device__ __nv_bfloat16 g_A[4][BB * LL * HH];
// B-side: V[b][var][(j*10+n)][k] bf16, var as above
__device__ __nv_bfloat16 g_Bv[BB][4][LL * NB * HH];

// ---------------------------------------------------------------------------
// helpers
// ---------------------------------------------------------------------------
__device__ __forceinline__ uint32_t smem_u32(const void* p) {
    uint32_t a;
    asm("{ .reg .u64 t; cvta.to.shared.u64 t, %1; cvt.u32.u64 %0, t; }"
        : "=r"(a) : "l"(p));
    return a;
}
__device__ __forceinline__ void ldsm_x4(uint32_t* r, uint32_t addr) {
    asm volatile("ldmatrix.sync.aligned.m8n8.x4.shared.b16 {%0,%1,%2,%3}, [%4];"
        : "=r"(r[0]), "=r"(r[1]), "=r"(r[2]), "=r"(r[3]) : "r"(addr));
}
__device__ __forceinline__ void mma16816(float* c, const uint32_t* a,
                                         const uint32_t* b) {
    asm volatile(
        "mma.sync.aligned.m16n8k16.row.col.f32.bf16.bf16.f32 "
        "{%0,%1,%2,%3}, {%4,%5,%6,%7}, {%8,%9}, {%0,%1,%2,%3};"
        : "+f"(c[0]), "+f"(c[1]), "+f"(c[2]), "+f"(c[3])
        : "r"(a[0]), "r"(a[1]), "r"(a[2]), "r"(a[3]), "r"(b[0]), "r"(b[1]));
}

// ---------------------------------------------------------------------------
// zero-init for split-K atomic accumulation
// ---------------------------------------------------------------------------
__global__ void zero_kernel()
{
    const int idx = blockIdx.x * blockDim.x + threadIdx.x;      // 0 .. 98303
    float4* p = (idx < 49152) ? (float4*)g_xi : (float4*)g_xj;
    const int off = (idx < 49152) ? idx : idx - 49152;
    p[off] = make_float4(0.f, 0.f, 0.f, 0.f);
}

// ---------------------------------------------------------------------------
// Kernel A: merged projection GEMM, M=768, N=512 (Wi|Wj), K=1280, split-K x3.
// ---------------------------------------------------------------------------
__global__ __launch_bounds__(256) void proj_kernel(
    const float* __restrict__ x,
    const float* __restrict__ Wi, const float* __restrict__ bi,
    const float* __restrict__ Wj, const float* __restrict__ bj)
{
    const int nglob0 = blockIdx.y * 64;
    const bool second = (nglob0 >= HH);
    const float* __restrict__ W    = second ? Wj : Wi;
    const float* __restrict__ bias = second ? bj : bi;
    float* __restrict__ out        = second ? g_xj : g_xi;
    const int n0 = second ? (nglob0 - HH) : nglob0;

    const int kz   = blockIdx.z;
    const int it0  = kz * 27;
    const int nIt  = (kz == 2) ? 26 : 27;

    __shared__ __align__(16) float As[16][68];
    __shared__ __align__(16) float Bs[16][68];

    const int tid = threadIdx.x;
    const int tx = tid & 15;
    const int ty = tid >> 4;
    const int m0 = blockIdx.x * 64;

    float acc[4][4] = {};

    for (int it = it0; it < it0 + nIt; it++) {
        const int k0 = it * 16;
        {
            const int kk = tid & 15;
            const int r  = tid >> 4;
            #pragma unroll
            for (int l = 0; l < 4; l++)
                As[kk][r + 16 * l] = x[(m0 + r + 16 * l) * DD + k0 + kk];
        }
        {
            const int n   = tid & 63;
            const int kk4 = tid >> 6;
            #pragma unroll
            for (int l = 0; l < 4; l++)
                Bs[kk4 + 4 * l][n] = W[(k0 + kk4 + 4 * l) * HH + n0 + n];
        }
        __syncthreads();

        #pragma unroll
        for (int kk = 0; kk < 16; kk++) {
            const float4 av = *(const float4*)&As[kk][ty * 4];
            const float4 bv = *(const float4*)&Bs[kk][tx * 4];
            const float a[4] = {av.x, av.y, av.z, av.w};
            const float b[4] = {bv.x, bv.y, bv.z, bv.w};
            #pragma unroll
            for (int i = 0; i < 4; i++)
                #pragma unroll
                for (int j = 0; j < 4; j++)
                    acc[i][j] += a[i] * b[j];
        }
        __syncthreads();
    }

    #pragma unroll
    for (int j = 0; j < 4; j++) {
        const float bv = (kz == 0) ? bias[n0 + tx * 4 + j] : 0.f;
        #pragma unroll
        for (int i = 0; i < 4; i++)
            atomicAdd(&out[(m0 + ty * 4 + i) * HH + n0 + tx * 4 + j],
                      acc[i][j] + bv);
    }
}

// ---------------------------------------------------------------------------
// split xi into sign-separated bf16 hi/lo variants
// ---------------------------------------------------------------------------
__global__ void split_xi_kernel()
{
    const int idx = blockIdx.x * 256 + threadIdx.x;
    const float f = g_xi[idx];
    const float p = fmaxf(f, 0.f);
    const float m = fminf(f, 0.f);
    const __nv_bfloat16 ph = __float2bfloat16_rn(p);
    const __nv_bfloat16 pl = __float2bfloat16_rn(p - __bfloat162float(ph));
    const __nv_bfloat16 mh = __float2bfloat16_rn(m);
    const __nv_bfloat16 ml = __float2bfloat16_rn(m - __bfloat162float(mh));
    g_A[0][idx] = ph; g_A[1][idx] = pl; g_A[2][idx] = mh; g_A[3][idx] = ml;
}

// ---------------------------------------------------------------------------
// build V[b][var][(j*10+n)][k] = sign-split(xj[b,j,k]) * Wo[k,n], bf16 hi/lo
// ---------------------------------------------------------------------------
__global__ void build_v_kernel(const float* __restrict__ Wo)
{
    const int bj = blockIdx.x;
    const int b  = bj / LL;
    const int j  = bj % LL;
    const int k  = threadIdx.x;

    const float f = g_xj[(b * LL + j) * HH + k];
    const float p = fmaxf(f, 0.f);
    const float m = fminf(f, 0.f);

    #pragma unroll
    for (int n = 0; n < NB; n++) {
        const float w  = Wo[k * NB + n];
        const float vp = p * w;
        const float vm = m * w;
        const __nv_bfloat16 ph = __float2bfloat16_rn(vp);
        const __nv_bfloat16 pl = __float2bfloat16_rn(vp - __bfloat162float(ph));
        const __nv_bfloat16 mh = __float2bfloat16_rn(vm);
        const __nv_bfloat16 ml = __float2bfloat16_rn(vm - __bfloat162float(mh));
        const size_t idx = (size_t)(j * NB + n) * HH + k;
        g_Bv[b][0][idx] = ph;
        g_Bv[b][1][idx] = pl;
        g_Bv[b][2][idx] = mh;
        g_Bv[b][3][idx] = ml;
    }
}

// ---------------------------------------------------------------------------
// pair MMA kernel (mma.sync bf16):
//   out[m, gc] = sum_{sign} (Ah+Al)[m,:] @ (Bh+Bl)[gc,:]^T  (3-term) + bo
// CTA tile 128x128, K=256 in 4 chunks of 64, 2 sign phases. 8 warps, each
// 32(m) x 64(n), accum 64 f32/thread. ldmatrix stride-72 pad: conflict-free.
// ---------------------------------------------------------------------------
#define LDA 72
#define PAIR_SMEM (4 * 128 * LDA * 2)   // 73728 bytes (A:2var + B:2var)

__global__ __launch_bounds__(256, 2) void pair_mma_kernel(
    const float* __restrict__ bo, float* __restrict__ out)
{
    extern __shared__ char dsm[];
    __nv_bfloat16* sA = (__nv_bfloat16*)dsm;                     // [2][128][72]
    __nv_bfloat16* sB = (__nv_bfloat16*)(dsm + 2 * 128 * LDA * 2);

    const int tid = threadIdx.x, wid = tid >> 5, lane = tid & 31;
    const int n0 = blockIdx.x * 128;        // over 3840 (j*10+n), per batch
    const int m0 = blockIdx.y * 128;        // over 768 (b*384+i)
    const int b  = (m0 >= LL) ? 1 : 0;
    const int m_off = (wid & 3) * 32;
    const int n_off = (wid >> 2) * 64;

    // ldmatrix per-lane offsets
    const int a_r = lane & 15;
    const int a_c = (lane >> 4) << 3;
    const int b_r = (lane & 7) + ((lane & 16) ? 8 : 0);
    const int b_c = (lane & 8) ? 8 : 0;

    const uint32_t sAu = smem_u32(sA);
    const uint32_t sBu = smem_u32(sB);

    float acc[2][8][4] = {};

    #pragma unroll
    for (int sign = 0; sign < 2; sign++) {
        const __nv_bfloat16* __restrict__ gAh = g_A[sign * 2];
        const __nv_bfloat16* __restrict__ gAl = g_A[sign * 2 + 1];
        const __nv_bfloat16* __restrict__ gBh = g_Bv[b][sign * 2];
        const __nv_bfloat16* __restrict__ gBl = g_Bv[b][sign * 2 + 1];

        for (int kc = 0; kc < 4; kc++) {
            __syncthreads();
            // stage A chunk: 2 vars x 128 rows x 64 k  (uint4 = 8 bf16)
            #pragma unroll
            for (int it = 0; it < 8; it++) {
                const int i = tid + it * 256;          // 0..2047
                const int var = i >> 10;
                const int row = (i >> 3) & 127;
                const int g   = i & 7;
                const __nv_bfloat16* src =
                    (var ? gAl : gAh) + (m0 + row) * HH + kc * 64 + g * 8;
                *(uint4*)(sA + (var * 128 + row) * LDA + g * 8) =
                    *(const uint4*)src;
            }
            // stage B chunk
            #pragma unroll
            for (int it = 0; it < 8; it++) {
                const int i = tid + it * 256;
                const int var = i >> 10;
                const int row = (i >> 3) & 127;
                const int g   = i & 7;
                const __nv_bfloat16* src =
                    (var ? gBl : gBh) + (n0 + row) * HH + kc * 64 + g * 8;
                *(uint4*)(sB + (var * 128 + row) * LDA + g * 8) =
                    *(const uint4*)src;
            }
            __syncthreads();

            #pragma unroll
            for (int ks = 0; ks < 4; ks++) {
                uint32_t ah[2][4], al[2][4];
                #pragma unroll
                for (int mt = 0; mt < 2; mt++) {
                    const uint32_t row = m_off + mt * 16 + a_r;
                    const uint32_t col = ks * 16 + a_c;
                    ldsm_x4(ah[mt], sAu + (row * LDA + col) * 2);
                    ldsm_x4(al[mt], sAu + ((128 + row) * LDA + col) * 2);
                }
                #pragma unroll
                for (int np = 0; np < 4; np++) {
                    uint32_t bh[4], bl[4];
                    const uint32_t row = n_off + np * 16 + b_r;
                    const uint32_t col = ks * 16 + b_c;
                    ldsm_x4(bh, sBu + (row * LDA + col) * 2);
                    ldsm_x4(bl, sBu + ((128 + row) * LDA + col) * 2);
                    #pragma unroll
                    for (int mt = 0; mt < 2; mt++) {
                        #pragma unroll
                        for (int nt = 0; nt < 2; nt++) {
                            float* c = acc[mt][np * 2 + nt];
                            mma16816(c, ah[mt], bh + nt * 2);
                            mma16816(c, ah[mt], bl + nt * 2);
                            mma16816(c, al[mt], bh + nt * 2);
                        }
                    }
                }
            }
        }
    }

    // epilogue: C layout m16n8 -> thread holds (row=tg, col=tig*2..+1) x2 rows
    const int tg = lane >> 2, tig = lane & 3;
    #pragma unroll
    for (int mt = 0; mt < 2; mt++) {
        #pragma unroll
        for (int np = 0; np < 4; np++) {
            #pragma unroll
            for (int nt = 0; nt < 2; nt++) {
                const int ncol = n0 + n_off + np * 16 + nt * 8 + tig * 2;
                const int bin = ncol % NB;           // even -> bin+1 <= 9
                const float b0v = bo[bin];
                const float b1v = bo[bin + 1];
                const float* c = acc[mt][np * 2 + nt];
                const int m = m0 + m_off + mt * 16 + tg;
                float* p0 = out + (size_t)m * (LL * NB) + ncol;
                *(float2*)p0 = make_float2(c[0] + b0v, c[1] + b1v);
                float* p1 = p0 + 8 * (size_t)(LL * NB);
                *(float2*)p1 = make_float2(c[2] + b0v, c[3] + b1v);
            }
        }
    }
}

// ---------------------------------------------------------------------------
// launch
// ---------------------------------------------------------------------------
extern "C" void kernel_launch(void* const* d_in, const int* in_sizes, int n_in,
                              void* d_out, int out_size)
{
    const float* x  = (const float*)d_in[0];
    const float* Wi = (const float*)d_in[1];
    const float* bi = (const float*)d_in[2];
    const float* Wj = (const float*)d_in[3];
    const float* bj = (const float*)d_in[4];
    const float* Wo = (const float*)d_in[5];
    const float* bo = (const float*)d_in[6];
    float* out = (float*)d_out;

    zero_kernel<<<384, 256>>>();

    dim3 gA(12, 8, 3);
    proj_kernel<<<gA, 256>>>(x, Wi, bi, Wj, bj);

    split_xi_kernel<<<768, 256>>>();
    build_v_kernel<<<768, 256>>>(Wo);

    cudaFuncSetAttribute(pair_mma_kernel,
                         cudaFuncAttributeMaxDynamicSharedMemorySize, PAIR_SMEM);
    dim3 gP(30, 6);
    pair_mma_kernel<<<gP, 256, PAIR_SMEM>>>(bo, out);
}

// round 5
// speedup vs baseline: 2.4631x; 1.1613x over previous
#include <cuda_runtime.h>
#include <cuda_bf16.h>
#include <cstdint>

#define BB 2
#define LL 384
#define DD 1280
#define HH 256
#define NB 10

// ---------------------------------------------------------------------------
// device globals (no allocation allowed)
// ---------------------------------------------------------------------------
// x split hi/lo: [2][768][1280] bf16
__device__ __nv_bfloat16 g_xs[2][BB * LL * DD];
// W transposed+split: [2][512][1280] bf16 (rows n: 0..255 = Wi cols, 256.. = Wj)
__device__ __nv_bfloat16 g_ws[2][512 * DD];
// proj split-K partials: [3][768][512] f32 (cols 0..255 = xi, 256..511 = xj)
__device__ float g_pp[3 * BB * LL * 512];
// A-side split: variants 0=h+, 1=l+, 2=h-, 3=l-   [768][256] bf16 each
__device__ __nv_bfloat16 g_A[4][BB * LL * HH];
// B-side: V[b][var][(j*10+n)][k] bf16
__device__ __nv_bfloat16 g_Bv[BB][4][LL * NB * HH];

// ---------------------------------------------------------------------------
// helpers
// ---------------------------------------------------------------------------
__device__ __forceinline__ uint32_t smem_u32(const void* p) {
    uint32_t a;
    asm("{ .reg .u64 t; cvta.to.shared.u64 t, %1; cvt.u32.u64 %0, t; }"
        : "=r"(a) : "l"(p));
    return a;
}
__device__ __forceinline__ void ldsm_x4(uint32_t* r, uint32_t addr) {
    asm volatile("ldmatrix.sync.aligned.m8n8.x4.shared.b16 {%0,%1,%2,%3}, [%4];"
        : "=r"(r[0]), "=r"(r[1]), "=r"(r[2]), "=r"(r[3]) : "r"(addr));
}
__device__ __forceinline__ void mma16816(float* c, const uint32_t* a,
                                         const uint32_t* b) {
    asm volatile(
        "mma.sync.aligned.m16n8k16.row.col.f32.bf16.bf16.f32 "
        "{%0,%1,%2,%3}, {%4,%5,%6,%7}, {%8,%9}, {%0,%1,%2,%3};"
        : "+f"(c[0]), "+f"(c[1]), "+f"(c[2]), "+f"(c[3])
        : "r"(a[0]), "r"(a[1]), "r"(a[2]), "r"(a[3]), "r"(b[0]), "r"(b[1]));
}
__device__ __forceinline__ void cp16(uint32_t dst, const void* src) {
    asm volatile("cp.async.cg.shared.global [%0], [%1], 16;"
                 :: "r"(dst), "l"(src));
}
__device__ __forceinline__ void cp_commit() {
    asm volatile("cp.async.commit_group;");
}
template <int N>
__device__ __forceinline__ void cp_wait() {
    asm volatile("cp.async.wait_group %0;" :: "n"(N));
}

// ---------------------------------------------------------------------------
// prep_x: split x (fp32) into bf16 hi/lo. 4 elements per thread.
// ---------------------------------------------------------------------------
__global__ void prep_x_kernel(const float* __restrict__ x)
{
    const int t = blockIdx.x * 256 + threadIdx.x;     // 0..245759
    const float4 v = *(const float4*)(x + t * 4);
    const float f[4] = {v.x, v.y, v.z, v.w};
    __nv_bfloat16 hi[4], lo[4];
    #pragma unroll
    for (int q = 0; q < 4; q++) {
        hi[q] = __float2bfloat16_rn(f[q]);
        lo[q] = __float2bfloat16_rn(f[q] - __bfloat162float(hi[q]));
    }
    *(uint2*)&g_xs[0][t * 4] = *(uint2*)hi;
    *(uint2*)&g_xs[1][t * 4] = *(uint2*)lo;
}

// ---------------------------------------------------------------------------
// prep_w: transpose W[k][n] -> g_ws[v][n][k] with hi/lo split.
// grid (16 n-tiles, 40 k-tiles), 256 threads, 32x32 smem tile.
// ---------------------------------------------------------------------------
__global__ void prep_w_kernel(const float* __restrict__ Wi,
                              const float* __restrict__ Wj)
{
    __shared__ float tile[32][33];
    const int n0 = blockIdx.x * 32;       // 0..480
    const int k0 = blockIdx.y * 32;       // 0..1248
    const int c  = threadIdx.x & 31;
    const int r0 = threadIdx.x >> 5;      // 0..7

    const bool second = (n0 >= HH);
    const float* __restrict__ W = second ? Wj : Wi;
    const int ncol = second ? (n0 - HH) : n0;

    #pragma unroll
    for (int p = 0; p < 4; p++) {
        const int r = r0 + p * 8;
        tile[r][c] = W[(k0 + r) * HH + ncol + c];
    }
    __syncthreads();
    #pragma unroll
    for (int p = 0; p < 4; p++) {
        const int r = r0 + p * 8;         // n within tile
        const float f = tile[c][r];       // transposed read
        const __nv_bfloat16 hi = __float2bfloat16_rn(f);
        const __nv_bfloat16 lo = __float2bfloat16_rn(f - __bfloat162float(hi));
        g_ws[0][(n0 + r) * DD + k0 + c] = hi;
        g_ws[1][(n0 + r) * DD + k0 + c] = lo;
    }
}

// ---------------------------------------------------------------------------
// proj MMA: partial[kz] = x_split @ ws_split^T  (3-chain bf16)
// CTA 64x64, K chunks of 64 (7/7/6 per kz). 8 warps, warp tile 16m x 32n.
// ---------------------------------------------------------------------------
#define PLDA 72

__global__ __launch_bounds__(256, 2) void proj_mma_kernel()
{
    __shared__ __nv_bfloat16 sA[2 * 64 * PLDA];
    __shared__ __nv_bfloat16 sB[2 * 64 * PLDA];

    const int tid = threadIdx.x, wid = tid >> 5, lane = tid & 31;
    const int m0 = blockIdx.x * 64;
    const int n0 = blockIdx.y * 64;
    const int kz = blockIdx.z;
    const int c0 = kz * 7, c1 = (kz == 2) ? 20 : (c0 + 7);

    const int m_off = (wid & 3) * 16;
    const int n_off = (wid >> 2) * 32;

    const int a_r = lane & 15;
    const int a_c = (lane >> 4) << 3;
    const int b_r = (lane & 7) + ((lane & 16) ? 8 : 0);
    const int b_c = (lane & 8) ? 8 : 0;

    const uint32_t sAu = smem_u32(sA);
    const uint32_t sBu = smem_u32(sB);

    float acc[4][4] = {};

    for (int ch = c0; ch < c1; ch++) {
        const int kg = ch * 64;
        __syncthreads();
        // stage A: 2var x 64 rows x 64k -> 1024 granules of 8 bf16
        #pragma unroll
        for (int it = 0; it < 4; it++) {
            const int i = tid + it * 256;
            const int var = i >> 9;
            const int row = (i >> 3) & 63;
            const int g   = i & 7;
            *(uint4*)(sA + (var * 64 + row) * PLDA + g * 8) =
                *(const uint4*)(g_xs[var] + (m0 + row) * DD + kg + g * 8);
        }
        #pragma unroll
        for (int it = 0; it < 4; it++) {
            const int i = tid + it * 256;
            const int var = i >> 9;
            const int row = (i >> 3) & 63;
            const int g   = i & 7;
            *(uint4*)(sB + (var * 64 + row) * PLDA + g * 8) =
                *(const uint4*)(g_ws[var] + (n0 + row) * DD + kg + g * 8);
        }
        __syncthreads();

        #pragma unroll
        for (int ks = 0; ks < 4; ks++) {
            uint32_t ah[4], al[4];
            {
                const uint32_t row = m_off + a_r;
                const uint32_t col = ks * 16 + a_c;
                ldsm_x4(ah, sAu + (row * PLDA + col) * 2);
                ldsm_x4(al, sAu + ((64 + row) * PLDA + col) * 2);
            }
            #pragma unroll
            for (int np = 0; np < 2; np++) {
                uint32_t bh[4], bl[4];
                const uint32_t row = n_off + np * 16 + b_r;
                const uint32_t col = ks * 16 + b_c;
                ldsm_x4(bh, sBu + (row * PLDA + col) * 2);
                ldsm_x4(bl, sBu + ((64 + row) * PLDA + col) * 2);
                #pragma unroll
                for (int nt = 0; nt < 2; nt++) {
                    float* c = acc[np * 2 + nt];
                    mma16816(c, ah, bh + nt * 2);
                    mma16816(c, ah, bl + nt * 2);
                    mma16816(c, al, bh + nt * 2);
                }
            }
        }
    }

    // epilogue: write partial slab (no atomics)
    const int tg = lane >> 2, tig = lane & 3;
    float* pp = g_pp + (size_t)kz * (BB * LL * 512);
    #pragma unroll
    for (int np = 0; np < 2; np++) {
        #pragma unroll
        for (int nt = 0; nt < 2; nt++) {
            const int col = n0 + n_off + np * 16 + nt * 8 + tig * 2;
            const int row = m0 + m_off + tg;
            const float* c = acc[np * 2 + nt];
            *(float2*)&pp[(size_t)row * 512 + col] = make_float2(c[0], c[1]);
            *(float2*)&pp[(size_t)(row + 8) * 512 + col] = make_float2(c[2], c[3]);
        }
    }
}

// ---------------------------------------------------------------------------
// split_xi: xi = sum of partials + bi  -> sign-split bf16 hi/lo variants
// ---------------------------------------------------------------------------
__global__ void split_xi_kernel(const float* __restrict__ bi)
{
    const int row = blockIdx.x;           // 0..767
    const int col = threadIdx.x;          // 0..255
    const size_t o = (size_t)row * 512 + col;
    const float f = g_pp[o] + g_pp[o + BB * LL * 512]
                  + g_pp[o + 2 * BB * LL * 512] + bi[col];
    const float p = fmaxf(f, 0.f);
    const float m = fminf(f, 0.f);
    const __nv_bfloat16 ph = __float2bfloat16_rn(p);
    const __nv_bfloat16 pl = __float2bfloat16_rn(p - __bfloat162float(ph));
    const __nv_bfloat16 mh = __float2bfloat16_rn(m);
    const __nv_bfloat16 ml = __float2bfloat16_rn(m - __bfloat162float(mh));
    const int idx = row * HH + col;
    g_A[0][idx] = ph; g_A[1][idx] = pl; g_A[2][idx] = mh; g_A[3][idx] = ml;
}

// ---------------------------------------------------------------------------
// build_v: xj = sum of partials + bj; V = sign-split(xj) * Wo hi/lo
// ---------------------------------------------------------------------------
__global__ void build_v_kernel(const float* __restrict__ Wo,
                               const float* __restrict__ bj)
{
    const int bjx = blockIdx.x;
    const int b  = bjx / LL;
    const int j  = bjx % LL;
    const int k  = threadIdx.x;

    const size_t o = (size_t)(b * LL + j) * 512 + 256 + k;
    const float f = g_pp[o] + g_pp[o + BB * LL * 512]
                  + g_pp[o + 2 * BB * LL * 512] + bj[k];
    const float p = fmaxf(f, 0.f);
    const float m = fminf(f, 0.f);

    #pragma unroll
    for (int n = 0; n < NB; n++) {
        const float w  = Wo[k * NB + n];
        const float vp = p * w;
        const float vm = m * w;
        const __nv_bfloat16 ph = __float2bfloat16_rn(vp);
        const __nv_bfloat16 pl = __float2bfloat16_rn(vp - __bfloat162float(ph));
        const __nv_bfloat16 mh = __float2bfloat16_rn(vm);
        const __nv_bfloat16 ml = __float2bfloat16_rn(vm - __bfloat162float(mh));
        const size_t idx = (size_t)(j * NB + n) * HH + k;
        g_Bv[b][0][idx] = ph;
        g_Bv[b][1][idx] = pl;
        g_Bv[b][2][idx] = mh;
        g_Bv[b][3][idx] = ml;
    }
}

// ---------------------------------------------------------------------------
// pair MMA kernel with cp.async double buffering.
// CTA 128x128, K logically 512 (2 signs x 256) in 16 chunks of 32.
// Buffer layout per buf: A [2var][128][40] bf16 + B [2var][128][40] bf16.
// ---------------------------------------------------------------------------
#define KLDA 40
#define ABYTES (2 * 128 * KLDA * 2)      // 20480
#define BUFB   (2 * ABYTES)              // 40960 per buffer
#define PAIR_SMEM (2 * BUFB)             // 81920

__global__ __launch_bounds__(256, 2) void pair_mma_kernel(
    const float* __restrict__ bo, float* __restrict__ out)
{
    extern __shared__ char dsm[];
    const uint32_t sbase = smem_u32(dsm);

    const int tid = threadIdx.x, wid = tid >> 5, lane = tid & 31;
    const int n0 = blockIdx.x * 128;
    const int m0 = blockIdx.y * 128;
    const int b  = (m0 >= LL) ? 1 : 0;
    const int m_off = (wid & 3) * 32;
    const int n_off = (wid >> 2) * 64;

    const int a_r = lane & 15;
    const int a_c = (lane >> 4) << 3;
    const int b_r = (lane & 7) + ((lane & 16) ? 8 : 0);
    const int b_c = (lane & 8) ? 8 : 0;

    // stage chunk ch into buffer bi (cp.async, 8 granules per thread)
    auto stage = [&](int ch, int bsel) {
        const int sign = ch >> 3;
        const int kb   = (ch & 7) * 32;               // k base within sign
        const uint32_t bufA = sbase + bsel * BUFB;
        const uint32_t bufB = bufA + ABYTES;
        #pragma unroll
        for (int it = 0; it < 4; it++) {
            const int i = tid + it * 256;             // 0..1023
            const int var = i >> 9;
            const int row = (i >> 2) & 127;
            const int g   = i & 3;
            cp16(bufA + (var * 128 + row) * (KLDA * 2) + g * 16,
                 g_A[sign * 2 + var] + (m0 + row) * HH + kb + g * 8);
        }
        #pragma unroll
        for (int it = 0; it < 4; it++) {
            const int i = tid + it * 256;
            const int var = i >> 9;
            const int row = (i >> 2) & 127;
            const int g   = i & 3;
            cp16(bufB + (var * 128 + row) * (KLDA * 2) + g * 16,
                 g_Bv[b][sign * 2 + var] + (n0 + row) * HH + kb + g * 8);
        }
        cp_commit();
    };

    float acc[2][8][4] = {};

    stage(0, 0);
    stage(1, 1);

    for (int ch = 0; ch < 16; ch++) {
        if (ch < 15) cp_wait<1>(); else cp_wait<0>();
        __syncthreads();

        const uint32_t bufA = sbase + (ch & 1) * BUFB;
        const uint32_t bufB = bufA + ABYTES;

        #pragma unroll
        for (int ks = 0; ks < 2; ks++) {
            uint32_t ah[2][4], al[2][4];
            #pragma unroll
            for (int mt = 0; mt < 2; mt++) {
                const uint32_t row = m_off + mt * 16 + a_r;
                const uint32_t col = ks * 16 + a_c;
                ldsm_x4(ah[mt], bufA + (row * KLDA + col) * 2);
                ldsm_x4(al[mt], bufA + ((128 + row) * KLDA + col) * 2);
            }
            #pragma unroll
            for (int np = 0; np < 4; np++) {
                uint32_t bh[4], bl[4];
                const uint32_t row = n_off + np * 16 + b_r;
                const uint32_t col = ks * 16 + b_c;
                ldsm_x4(bh, bufB + (row * KLDA + col) * 2);
                ldsm_x4(bl, bufB + ((128 + row) * KLDA + col) * 2);
                #pragma unroll
                for (int mt = 0; mt < 2; mt++) {
                    #pragma unroll
                    for (int nt = 0; nt < 2; nt++) {
                        float* c = acc[mt][np * 2 + nt];
                        mma16816(c, ah[mt], bh + nt * 2);
                        mma16816(c, ah[mt], bl + nt * 2);
                        mma16816(c, al[mt], bh + nt * 2);
                    }
                }
            }
        }
        __syncthreads();
        if (ch + 2 < 16) stage(ch + 2, ch & 1);
    }

    // epilogue
    const int tg = lane >> 2, tig = lane & 3;
    #pragma unroll
    for (int mt = 0; mt < 2; mt++) {
        #pragma unroll
        for (int np = 0; np < 4; np++) {
            #pragma unroll
            for (int nt = 0; nt < 2; nt++) {
                const int ncol = n0 + n_off + np * 16 + nt * 8 + tig * 2;
                const int bin = ncol % NB;
                const float b0v = bo[bin];
                const float b1v = bo[bin + 1];
                const float* c = acc[mt][np * 2 + nt];
                const int m = m0 + m_off + mt * 16 + tg;
                float* p0 = out + (size_t)m * (LL * NB) + ncol;
                *(float2*)p0 = make_float2(c[0] + b0v, c[1] + b1v);
                float* p1 = p0 + 8 * (size_t)(LL * NB);
                *(float2*)p1 = make_float2(c[2] + b0v, c[3] + b1v);
            }
        }
    }
}

// ---------------------------------------------------------------------------
// launch
// ---------------------------------------------------------------------------
extern "C" void kernel_launch(void* const* d_in, const int* in_sizes, int n_in,
                              void* d_out, int out_size)
{
    const float* x  = (const float*)d_in[0];
    const float* Wi = (const float*)d_in[1];
    const float* bi = (const float*)d_in[2];
    const float* Wj = (const float*)d_in[3];
    const float* bj = (const float*)d_in[4];
    const float* Wo = (const float*)d_in[5];
    const float* bo = (const float*)d_in[6];
    float* out = (float*)d_out;

    prep_x_kernel<<<960, 256>>>(x);
    prep_w_kernel<<<dim3(16, 40), 256>>>(Wi, Wj);

    dim3 gA(12, 8, 3);
    proj_mma_kernel<<<gA, 256>>>();

    split_xi_kernel<<<768, 256>>>(bi);
    build_v_kernel<<<768, 256>>>(Wo, bj);

    cudaFuncSetAttribute(pair_mma_kernel,
                         cudaFuncAttributeMaxDynamicSharedMemorySize, PAIR_SMEM);
    dim3 gP(30, 6);
    pair_mma_kernel<<<gP, 256, PAIR_SMEM>>>(bo, out);
}

// round 6
// speedup vs baseline: 2.6083x; 1.0590x over previous
#include <cuda_runtime.h>
#include <cuda_bf16.h>
#include <cstdint>

#define BB 2
#define LL 384
#define DD 1280
#define HH 256
#define NB 10

// ---------------------------------------------------------------------------
// device globals (no allocation allowed)
// ---------------------------------------------------------------------------
__device__ __nv_bfloat16 g_xs[2][BB * LL * DD];        // x split hi/lo
__device__ __nv_bfloat16 g_ws[2][512 * DD];            // W^T split hi/lo
__device__ float g_pp[3 * BB * LL * 512];              // proj split-K partials
__device__ __nv_bfloat16 g_A[4][BB * LL * HH];         // xi: h+, l+, h-, l-
__device__ __nv_bfloat16 g_Bv[BB][4][LL * NB * HH];    // V variants

// ---------------------------------------------------------------------------
// helpers
// ---------------------------------------------------------------------------
__device__ __forceinline__ uint32_t smem_u32(const void* p) {
    uint32_t a;
    asm("{ .reg .u64 t; cvta.to.shared.u64 t, %1; cvt.u32.u64 %0, t; }"
        : "=r"(a) : "l"(p));
    return a;
}
__device__ __forceinline__ void ldsm_x4(uint32_t* r, uint32_t addr) {
    asm volatile("ldmatrix.sync.aligned.m8n8.x4.shared.b16 {%0,%1,%2,%3}, [%4];"
        : "=r"(r[0]), "=r"(r[1]), "=r"(r[2]), "=r"(r[3]) : "r"(addr));
}
__device__ __forceinline__ void mma16816(float* c, const uint32_t* a,
                                         const uint32_t* b) {
    asm volatile(
        "mma.sync.aligned.m16n8k16.row.col.f32.bf16.bf16.f32 "
        "{%0,%1,%2,%3}, {%4,%5,%6,%7}, {%8,%9}, {%0,%1,%2,%3};"
        : "+f"(c[0]), "+f"(c[1]), "+f"(c[2]), "+f"(c[3])
        : "r"(a[0]), "r"(a[1]), "r"(a[2]), "r"(a[3]), "r"(b[0]), "r"(b[1]));
}
__device__ __forceinline__ void cp16(uint32_t dst, const void* src) {
    asm volatile("cp.async.cg.shared.global [%0], [%1], 16;"
                 :: "r"(dst), "l"(src));
}
__device__ __forceinline__ void cp_commit() {
    asm volatile("cp.async.commit_group;");
}
template <int N>
__device__ __forceinline__ void cp_wait() {
    asm volatile("cp.async.wait_group %0;" :: "n"(N));
}

// ---------------------------------------------------------------------------
// prep: fused  [blocks 0..959] split x into bf16 hi/lo (4 elem/thread)
//              [blocks 960..1599] transpose+split W -> g_ws
// ---------------------------------------------------------------------------
__global__ void prep_kernel(const float* __restrict__ x,
                            const float* __restrict__ Wi,
                            const float* __restrict__ Wj)
{
    if (blockIdx.x < 960) {
        const int t = blockIdx.x * 256 + threadIdx.x;
        const float4 v = *(const float4*)(x + t * 4);
        const float f[4] = {v.x, v.y, v.z, v.w};
        __nv_bfloat16 hi[4], lo[4];
        #pragma unroll
        for (int q = 0; q < 4; q++) {
            hi[q] = __float2bfloat16_rn(f[q]);
            lo[q] = __float2bfloat16_rn(f[q] - __bfloat162float(hi[q]));
        }
        *(uint2*)&g_xs[0][t * 4] = *(uint2*)hi;
        *(uint2*)&g_xs[1][t * 4] = *(uint2*)lo;
    } else {
        __shared__ float tile[32][33];
        const int wb = blockIdx.x - 960;
        const int n0 = (wb & 15) * 32;
        const int k0 = (wb >> 4) * 32;
        const int c  = threadIdx.x & 31;
        const int r0 = threadIdx.x >> 5;

        const bool second = (n0 >= HH);
        const float* __restrict__ W = second ? Wj : Wi;
        const int ncol = second ? (n0 - HH) : n0;

        #pragma unroll
        for (int p = 0; p < 4; p++) {
            const int r = r0 + p * 8;
            tile[r][c] = W[(k0 + r) * HH + ncol + c];
        }
        __syncthreads();
        #pragma unroll
        for (int p = 0; p < 4; p++) {
            const int r = r0 + p * 8;
            const float f = tile[c][r];
            const __nv_bfloat16 hi = __float2bfloat16_rn(f);
            const __nv_bfloat16 lo =
                __float2bfloat16_rn(f - __bfloat162float(hi));
            g_ws[0][(n0 + r) * DD + k0 + c] = hi;
            g_ws[1][(n0 + r) * DD + k0 + c] = lo;
        }
    }
}

// ---------------------------------------------------------------------------
// proj MMA: partial[kz] = x_split @ ws_split^T (3-chain bf16), cp.async
// double-buffered. CTA 64x64, K chunks of 64 (7/7/6 per kz split).
// buffer: A [2var][64][72] + B same; 36864 B per buffer, 2 buffers.
// ---------------------------------------------------------------------------
#define PLDA 72
#define PJ_ABYTES (2 * 64 * PLDA * 2)       // 18432
#define PJ_BUFB   (2 * PJ_ABYTES)           // 36864
#define PJ_SMEM   (2 * PJ_BUFB)             // 73728

__global__ __launch_bounds__(256, 2) void proj_mma_kernel()
{
    extern __shared__ char dsm[];
    const uint32_t sbase = smem_u32(dsm);

    const int tid = threadIdx.x, wid = tid >> 5, lane = tid & 31;
    const int m0 = blockIdx.x * 64;
    const int n0 = blockIdx.y * 64;
    const int kz = blockIdx.z;
    const int c0 = kz * 7;
    const int nc = (kz == 2) ? 6 : 7;

    const int m_off = (wid & 3) * 16;
    const int n_off = (wid >> 2) * 32;

    const int a_r = lane & 15;
    const int a_c = (lane >> 4) << 3;
    const int b_r = (lane & 7) + ((lane & 16) ? 8 : 0);
    const int b_c = (lane & 8) ? 8 : 0;

    auto stage = [&](int ch, int bsel) {
        const int kg = ch * 64;
        const uint32_t bufA = sbase + bsel * PJ_BUFB;
        const uint32_t bufB = bufA + PJ_ABYTES;
        #pragma unroll
        for (int it = 0; it < 4; it++) {
            const int i = tid + it * 256;            // 0..1023
            const int var = i >> 9;
            const int row = (i >> 3) & 63;
            const int g   = i & 7;
            cp16(bufA + (var * 64 + row) * (PLDA * 2) + g * 16,
                 g_xs[var] + (m0 + row) * DD + kg + g * 8);
        }
        #pragma unroll
        for (int it = 0; it < 4; it++) {
            const int i = tid + it * 256;
            const int var = i >> 9;
            const int row = (i >> 3) & 63;
            const int g   = i & 7;
            cp16(bufB + (var * 64 + row) * (PLDA * 2) + g * 16,
                 g_ws[var] + (n0 + row) * DD + kg + g * 8);
        }
        cp_commit();
    };

    float acc[4][4] = {};

    stage(c0, 0);
    stage(c0 + 1, 1);

    for (int q = 0; q < nc; q++) {
        if (q < nc - 1) cp_wait<1>(); else cp_wait<0>();
        __syncthreads();

        const uint32_t bufA = sbase + (q & 1) * PJ_BUFB;
        const uint32_t bufB = bufA + PJ_ABYTES;

        #pragma unroll
        for (int ks = 0; ks < 4; ks++) {
            uint32_t ah[4], al[4];
            {
                const uint32_t row = m_off + a_r;
                const uint32_t col = ks * 16 + a_c;
                ldsm_x4(ah, bufA + (row * PLDA + col) * 2);
                ldsm_x4(al, bufA + ((64 + row) * PLDA + col) * 2);
            }
            #pragma unroll
            for (int np = 0; np < 2; np++) {
                uint32_t bh[4], bl[4];
                const uint32_t row = n_off + np * 16 + b_r;
                const uint32_t col = ks * 16 + b_c;
                ldsm_x4(bh, bufB + (row * PLDA + col) * 2);
                ldsm_x4(bl, bufB + ((64 + row) * PLDA + col) * 2);
                #pragma unroll
                for (int nt = 0; nt < 2; nt++) {
                    float* c = acc[np * 2 + nt];
                    mma16816(c, ah, bh + nt * 2);
                    mma16816(c, ah, bl + nt * 2);
                    mma16816(c, al, bh + nt * 2);
                }
            }
        }
        __syncthreads();
        if (q + 2 < nc) stage(c0 + q + 2, q & 1);
    }

    const int tg = lane >> 2, tig = lane & 3;
    float* pp = g_pp + (size_t)kz * (BB * LL * 512);
    #pragma unroll
    for (int np = 0; np < 2; np++) {
        #pragma unroll
        for (int nt = 0; nt < 2; nt++) {
            const int col = n0 + n_off + np * 16 + nt * 8 + tig * 2;
            const int row = m0 + m_off + tg;
            const float* c = acc[np * 2 + nt];
            *(float2*)&pp[(size_t)row * 512 + col] = make_float2(c[0], c[1]);
            *(float2*)&pp[(size_t)(row + 8) * 512 + col] =
                make_float2(c[2], c[3]);
        }
    }
}

// ---------------------------------------------------------------------------
// postproj (fused): block r = b*384+j.
//  part 1: xi[r] = sum partials + bi -> sign-split hi/lo into g_A
//  part 2: xj[r] = sum partials + bj; V[r] = sign-split(xj)*Wo -> g_Bv
//  part 2 mapping: thread t: half = t>>7 -> n in [half*5, half*5+5),
//                  tk = t&127 -> k0 = 2*tk; stores bf16x2 along k (STG.32).
// ---------------------------------------------------------------------------
#define SLAB (BB * LL * 512)

__global__ __launch_bounds__(256) void postproj_kernel(
    const float* __restrict__ bi, const float* __restrict__ bj,
    const float* __restrict__ Wo)
{
    const int r = blockIdx.x;              // 0..767
    const int b = r / LL;
    const int j = r % LL;
    const int t = threadIdx.x;

    // ---- part 1: xi split (col = t) ----
    {
        const size_t o = (size_t)r * 512 + t;
        const float f = g_pp[o] + g_pp[o + SLAB] + g_pp[o + 2 * SLAB] + bi[t];
        const float p = fmaxf(f, 0.f);
        const float m = fminf(f, 0.f);
        const __nv_bfloat16 ph = __float2bfloat16_rn(p);
        const __nv_bfloat16 pl =
            __float2bfloat16_rn(p - __bfloat162float(ph));
        const __nv_bfloat16 mh = __float2bfloat16_rn(m);
        const __nv_bfloat16 ml =
            __float2bfloat16_rn(m - __bfloat162float(mh));
        const int idx = r * HH + t;
        g_A[0][idx] = ph; g_A[1][idx] = pl;
        g_A[2][idx] = mh; g_A[3][idx] = ml;
    }

    // ---- part 2: V build, 2 adjacent k per thread, 5 bins per thread ----
    const int half = t >> 7;               // 0 or 1
    const int k0   = (t & 127) * 2;

    const size_t o = (size_t)r * 512 + 256 + k0;
    const float f0 = g_pp[o] + g_pp[o + SLAB] + g_pp[o + 2 * SLAB] + bj[k0];
    const float f1 = g_pp[o + 1] + g_pp[o + 1 + SLAB]
                   + g_pp[o + 1 + 2 * SLAB] + bj[k0 + 1];
    const float p0 = fmaxf(f0, 0.f), m0v = fminf(f0, 0.f);
    const float p1 = fmaxf(f1, 0.f), m1v = fminf(f1, 0.f);

    #pragma unroll
    for (int q = 0; q < 5; q++) {
        const int n = half * 5 + q;
        const float w0 = Wo[k0 * NB + n];
        const float w1 = Wo[(k0 + 1) * NB + n];

        const float vp0 = p0 * w0,  vp1 = p1 * w1;
        const float vm0 = m0v * w0, vm1 = m1v * w1;

        const __nv_bfloat162 ph = __floats2bfloat162_rn(vp0, vp1);
        const __nv_bfloat162 pl = __floats2bfloat162_rn(
            vp0 - __low2float(ph), vp1 - __high2float(ph));
        const __nv_bfloat162 mh = __floats2bfloat162_rn(vm0, vm1);
        const __nv_bfloat162 ml = __floats2bfloat162_rn(
            vm0 - __low2float(mh), vm1 - __high2float(mh));

        const size_t idx = (size_t)(j * NB + n) * HH + k0;
        *(__nv_bfloat162*)&g_Bv[b][0][idx] = ph;
        *(__nv_bfloat162*)&g_Bv[b][1][idx] = pl;
        *(__nv_bfloat162*)&g_Bv[b][2][idx] = mh;
        *(__nv_bfloat162*)&g_Bv[b][3][idx] = ml;
    }
}

// ---------------------------------------------------------------------------
// pair MMA kernel with cp.async double buffering (unchanged from R5).
// ---------------------------------------------------------------------------
#define KLDA 40
#define ABYTES (2 * 128 * KLDA * 2)      // 20480
#define BUFB   (2 * ABYTES)              // 40960
#define PAIR_SMEM (2 * BUFB)             // 81920

__global__ __launch_bounds__(256, 2) void pair_mma_kernel(
    const float* __restrict__ bo, float* __restrict__ out)
{
    extern __shared__ char dsm[];
    const uint32_t sbase = smem_u32(dsm);

    const int tid = threadIdx.x, wid = tid >> 5, lane = tid & 31;
    const int n0 = blockIdx.x * 128;
    const int m0 = blockIdx.y * 128;
    const int b  = (m0 >= LL) ? 1 : 0;
    const int m_off = (wid & 3) * 32;
    const int n_off = (wid >> 2) * 64;

    const int a_r = lane & 15;
    const int a_c = (lane >> 4) << 3;
    const int b_r = (lane & 7) + ((lane & 16) ? 8 : 0);
    const int b_c = (lane & 8) ? 8 : 0;

    auto stage = [&](int ch, int bsel) {
        const int sign = ch >> 3;
        const int kb   = (ch & 7) * 32;
        const uint32_t bufA = sbase + bsel * BUFB;
        const uint32_t bufB = bufA + ABYTES;
        #pragma unroll
        for (int it = 0; it < 4; it++) {
            const int i = tid + it * 256;
            const int var = i >> 9;
            const int row = (i >> 2) & 127;
            const int g   = i & 3;
            cp16(bufA + (var * 128 + row) * (KLDA * 2) + g * 16,
                 g_A[sign * 2 + var] + (m0 + row) * HH + kb + g * 8);
        }
        #pragma unroll
        for (int it = 0; it < 4; it++) {
            const int i = tid + it * 256;
            const int var = i >> 9;
            const int row = (i >> 2) & 127;
            const int g   = i & 3;
            cp16(bufB + (var * 128 + row) * (KLDA * 2) + g * 16,
                 g_Bv[b][sign * 2 + var] + (n0 + row) * HH + kb + g * 8);
        }
        cp_commit();
    };

    float acc[2][8][4] = {};

    stage(0, 0);
    stage(1, 1);

    for (int ch = 0; ch < 16; ch++) {
        if (ch < 15) cp_wait<1>(); else cp_wait<0>();
        __syncthreads();

        const uint32_t bufA = sbase + (ch & 1) * BUFB;
        const uint32_t bufB = bufA + ABYTES;

        #pragma unroll
        for (int ks = 0; ks < 2; ks++) {
            uint32_t ah[2][4], al[2][4];
            #pragma unroll
            for (int mt = 0; mt < 2; mt++) {
                const uint32_t row = m_off + mt * 16 + a_r;
                const uint32_t col = ks * 16 + a_c;
                ldsm_x4(ah[mt], bufA + (row * KLDA + col) * 2);
                ldsm_x4(al[mt], bufA + ((128 + row) * KLDA + col) * 2);
            }
            #pragma unroll
            for (int np = 0; np < 4; np++) {
                uint32_t bh[4], bl[4];
                const uint32_t row = n_off + np * 16 + b_r;
                const uint32_t col = ks * 16 + b_c;
                ldsm_x4(bh, bufB + (row * KLDA + col) * 2);
                ldsm_x4(bl, bufB + ((128 + row) * KLDA + col) * 2);
                #pragma unroll
                for (int mt = 0; mt < 2; mt++) {
                    #pragma unroll
                    for (int nt = 0; nt < 2; nt++) {
                        float* c = acc[mt][np * 2 + nt];
                        mma16816(c, ah[mt], bh + nt * 2);
                        mma16816(c, ah[mt], bl + nt * 2);
                        mma16816(c, al[mt], bh + nt * 2);
                    }
                }
            }
        }
        __syncthreads();
        if (ch + 2 < 16) stage(ch + 2, ch & 1);
    }

    const int tg = lane >> 2, tig = lane & 3;
    #pragma unroll
    for (int mt = 0; mt < 2; mt++) {
        #pragma unroll
        for (int np = 0; np < 4; np++) {
            #pragma unroll
            for (int nt = 0; nt < 2; nt++) {
                const int ncol = n0 + n_off + np * 16 + nt * 8 + tig * 2;
                const int bin = ncol % NB;
                const float b0v = bo[bin];
                const float b1v = bo[bin + 1];
                const float* c = acc[mt][np * 2 + nt];
                const int m = m0 + m_off + mt * 16 + tg;
                float* p0 = out + (size_t)m * (LL * NB) + ncol;
                *(float2*)p0 = make_float2(c[0] + b0v, c[1] + b1v);
                float* p1 = p0 + 8 * (size_t)(LL * NB);
                *(float2*)p1 = make_float2(c[2] + b0v, c[3] + b1v);
            }
        }
    }
}

// ---------------------------------------------------------------------------
// launch
// ---------------------------------------------------------------------------
extern "C" void kernel_launch(void* const* d_in, const int* in_sizes, int n_in,
                              void* d_out, int out_size)
{
    const float* x  = (const float*)d_in[0];
    const float* Wi = (const float*)d_in[1];
    const float* bi = (const float*)d_in[2];
    const float* Wj = (const float*)d_in[3];
    const float* bj = (const float*)d_in[4];
    const float* Wo = (const float*)d_in[5];
    const float* bo = (const float*)d_in[6];
    float* out = (float*)d_out;

    prep_kernel<<<1600, 256>>>(x, Wi, Wj);

    cudaFuncSetAttribute(proj_mma_kernel,
                         cudaFuncAttributeMaxDynamicSharedMemorySize, PJ_SMEM);
    dim3 gA(12, 8, 3);
    proj_mma_kernel<<<gA, 256, PJ_SMEM>>>();

    postproj_kernel<<<768, 256>>>(bi, bj, Wo);

    cudaFuncSetAttribute(pair_mma_kernel,
                         cudaFuncAttributeMaxDynamicSharedMemorySize, PAIR_SMEM);
    dim3 gP(30, 6);
    pair_mma_kernel<<<gP, 256, PAIR_SMEM>>>(bo, out);
}